// round 5
// baseline (speedup 1.0000x reference)
#include <cuda_runtime.h>

#define RS2 0.7071067811865476f
#define TAU_V 0.05f

constexpr int SH = 33;
constexpr int SD = 1089;             // 33*33 ; both ≡1 mod 32 → conflict-free strided access
constexpr int TILE_F = 32 * SD;      // 34848 floats = 139392 B
constexpr int NTHREADS = 512;

// valid level-1 band-block slots (slot = d3*16 + h3*4 + w3, excluding lll octant)
__device__ __constant__ unsigned char VSLOT[56] = {
    2,3,6,7,8,9,10,11,12,13,14,15,18,19,22,23,
    24,25,26,27,28,29,30,31,32,33,34,35,36,37,38,39,
    40,41,42,43,44,45,46,47,48,49,50,51,52,53,54,55,
    56,57,58,59,60,61,62,63
};

extern __shared__ float smem[];

// ---- in-place Haar line transforms, compile-time stride ----
template<int N, int SLINE>
__device__ __forceinline__ void line_fwd(float* p) {
    float v[N];
#pragma unroll
    for (int k = 0; k < N; k++) v[k] = p[k * SLINE];
#pragma unroll
    for (int i = 0; i < N / 2; i++) {
        p[i * SLINE]         = (v[2*i] + v[2*i+1]) * RS2;
        p[(i + N/2) * SLINE] = (v[2*i] - v[2*i+1]) * RS2;
    }
}
template<int N, int SLINE>
__device__ __forceinline__ void line_inv(float* p) {
    float v[N];
#pragma unroll
    for (int k = 0; k < N; k++) v[k] = p[k * SLINE];
#pragma unroll
    for (int i = 0; i < N / 2; i++) {
        p[(2*i)   * SLINE] = (v[i] + v[i + N/2]) * RS2;
        p[(2*i+1) * SLINE] = (v[i] - v[i + N/2]) * RS2;
    }
}

template<int N, int SLINE, int SA, int SB, int NA, int NB, bool FWD>
__device__ __forceinline__ void dwt_pass(float* T, int tid) {
#pragma unroll
    for (int li = tid; li < NA * NB; li += NTHREADS) {
        int a = li / NB, b = li % NB;        // NB is a power of two → shifts
        float* p = T + a * SA + b * SB;
        if (FWD) line_fwd<N, SLINE>(p); else line_inv<N, SLINE>(p);
    }
}

// ---- 2D Haar pyramid fwd + soft-threshold + inv, on v[64] in registers ----
__device__ __forceinline__ void pyramid(float* v) {
#pragma unroll
    for (int lev = 0; lev < 3; lev++) {
        const int S = 8 >> lev, H = S >> 1;
#pragma unroll
        for (int j = 0; j < S; j++) {
            float t[4], u[4];
#pragma unroll
            for (int i = 0; i < H; i++) {
                float a = v[(2*i)*8+j], b = v[(2*i+1)*8+j];
                t[i] = (a + b) * RS2; u[i] = (a - b) * RS2;
            }
#pragma unroll
            for (int i = 0; i < H; i++) { v[i*8+j] = t[i]; v[(i+H)*8+j] = u[i]; }
        }
#pragma unroll
        for (int i = 0; i < S; i++) {
            float t[4], u[4];
#pragma unroll
            for (int j = 0; j < H; j++) {
                float a = v[i*8+2*j], b = v[i*8+2*j+1];
                t[j] = (a + b) * RS2; u[j] = (a - b) * RS2;
            }
#pragma unroll
            for (int j = 0; j < H; j++) { v[i*8+j] = t[j]; v[i*8+j+H] = u[j]; }
        }
    }
#pragma unroll
    for (int e = 1; e < 64; e++)
        v[e] = copysignf(fmaxf(fabsf(v[e]) - TAU_V, 0.0f), v[e]);
#pragma unroll
    for (int lev = 2; lev >= 0; lev--) {
        const int S = 8 >> lev, H = S >> 1;
#pragma unroll
        for (int i = 0; i < S; i++) {
            float t[4], u[4];
#pragma unroll
            for (int j = 0; j < H; j++) {
                float lo = v[i*8+j], hi = v[i*8+j+H];
                t[j] = (lo + hi) * RS2; u[j] = (lo - hi) * RS2;
            }
#pragma unroll
            for (int j = 0; j < H; j++) { v[i*8+2*j] = t[j]; v[i*8+2*j+1] = u[j]; }
        }
#pragma unroll
        for (int j = 0; j < S; j++) {
            float t[4], u[4];
#pragma unroll
            for (int i = 0; i < H; i++) {
                float lo = v[i*8+j], hi = v[(i+H)*8+j];
                t[i] = (lo + hi) * RS2; u[i] = (lo - hi) * RS2;
            }
#pragma unroll
            for (int i = 0; i < H; i++) { v[(2*i)*8+j] = t[i]; v[(2*i+1)*8+j] = u[i]; }
        }
    }
}

// one bandlet group: compute per (block,normal,slice), 3 ordered writeback phases.
// NOTE: no trailing barrier — successive groups touch disjoint blocks.
__device__ __forceinline__ void bandlet_group(float* T, int nrm, bool active,
                                              int bd, int bh, int bw, int s) {
    float v[64];
    if (active) {
        if (nrm == 0) {
            const float* p = T + (bd+s)*SD + bh*SH + bw;
#pragma unroll
            for (int i = 0; i < 8; i++)
#pragma unroll
                for (int j = 0; j < 8; j++) v[i*8+j] = p[i*SH + j];
        } else if (nrm == 1) {
            const float* p = T + bd*SD + (bh+s)*SH + bw;
#pragma unroll
            for (int i = 0; i < 8; i++)
#pragma unroll
                for (int j = 0; j < 8; j++) v[i*8+j] = p[i*SD + j];
        } else {
            const float* p = T + bd*SD + bh*SH + bw + s;
#pragma unroll
            for (int i = 0; i < 8; i++)
#pragma unroll
                for (int j = 0; j < 8; j++) v[i*8+j] = p[i*SD + j*SH];
        }
        pyramid(v);
    }
    __syncthreads();
    if (active && nrm == 0) {
        float* p = T + (bd+s)*SD + bh*SH + bw;
#pragma unroll
        for (int i = 0; i < 8; i++)
#pragma unroll
            for (int j = 0; j < 8; j++) p[i*SH + j] = v[i*8+j];
    }
    __syncthreads();
    if (active && nrm == 1) {
        float* p = T + bd*SD + (bh+s)*SH + bw;
#pragma unroll
        for (int i = 0; i < 8; i++)
#pragma unroll
            for (int j = 0; j < 8; j++) p[i*SD + j] += v[i*8+j];
    }
    __syncthreads();
    if (active && nrm == 2) {
        float* p = T + bd*SD + bh*SH + bw + s;
#pragma unroll
        for (int i = 0; i < 8; i++)
#pragma unroll
            for (int j = 0; j < 8; j++)
                p[i*SD + j*SH] = (p[i*SD + j*SH] + v[i*8+j]) * (1.0f / 3.0f);
    }
}

__global__ __launch_bounds__(NTHREADS, 1)
void bandlet3d_kernel(const float* __restrict__ x, float* __restrict__ y) {
    float* T = smem;
    const int tid = threadIdx.x;

    const int bc = blockIdx.x;
    const int batch = bc / 125;
    const int rem = bc - batch * 125;
    const int td = rem / 25;
    const int th = (rem / 5) % 5;
    const int tw = rem % 5;
    const long long gbase = (long long)batch * 4096000LL
                          + (long long)td * 32 * 25600 + th * 32 * 160 + tw * 32;

    // ---- fused: global load (float4) + forward level-1 w-transform in registers ----
#pragma unroll
    for (int l = tid; l < 1024; l += NTHREADS) {
        int h = l & 31, d = l >> 5;
        const float4* g = reinterpret_cast<const float4*>(x + gbase + d*25600 + h*160);
        float v[32];
#pragma unroll
        for (int k = 0; k < 8; k++) {
            float4 q = g[k];
            v[4*k] = q.x; v[4*k+1] = q.y; v[4*k+2] = q.z; v[4*k+3] = q.w;
        }
        float* p = T + d*SD + h*SH;
#pragma unroll
        for (int i = 0; i < 16; i++) {
            p[i]      = (v[2*i] + v[2*i+1]) * RS2;
            p[i + 16] = (v[2*i] - v[2*i+1]) * RS2;
        }
    }
    __syncthreads();

    // forward level-1 h and d
    dwt_pass<32, SH, SD, 1, 32, 32, true>(T, tid); __syncthreads();
    dwt_pass<32, SD, SH, 1, 32, 32, true>(T, tid); __syncthreads();

    // ---- level-1 bandlet: 56 blocks in groups of 21/21/14 ----
#pragma unroll 1
    for (int g = 0; g < 3; g++) {
        const int base = g * 21;
        const int nblk = (g == 2) ? 14 : 21;
        const int ntask = nblk * 8;
        int nrm = 0, s = 0, bd = 0, bh = 0, bw = 0;
        bool active = (tid < 3 * ntask);
        if (active) {
            nrm = tid / ntask;
            int r = tid - nrm * ntask;
            int bg = r >> 3; s = r & 7;
            int slot = VSLOT[base + bg];
            bd = ((slot >> 4) & 3) * 8;
            bh = ((slot >> 2) & 3) * 8;
            bw = (slot & 3) * 8;
        }
        bandlet_group(T, nrm, active, bd, bh, bw, s);
    }
    // no barrier needed: fwd level-2 touches only the lll region (disjoint from band blocks)

    // forward level-2 (w,h,d on [0:16)^3)
    dwt_pass<16, 1,  SD, SH, 16, 16, true>(T, tid); __syncthreads();
    dwt_pass<16, SH, SD, 1,  16, 16, true>(T, tid); __syncthreads();
    dwt_pass<16, SD, SH, 1,  16, 16, true>(T, tid); __syncthreads();

    // ---- level-2 bandlet: 7 blocks, 168 tasks ----
    {
        int nrm = 0, s = 0, bd = 0, bh = 0, bw = 0;
        bool active = (tid < 168);
        if (active) {
            nrm = tid / 56;
            int r = tid - nrm * 56;
            int bg = r >> 3; s = r & 7;
            int slot = bg + 1;
            bd = ((slot >> 2) & 1) * 8;
            bh = ((slot >> 1) & 1) * 8;
            bw = (slot & 1) * 8;
        }
        bandlet_group(T, nrm, active, bd, bh, bw, s);
    }
    __syncthreads();   // idwt level-2 reads the band blocks just written

    // inverse level-2 (w,h,d)
    dwt_pass<16, 1,  SD, SH, 16, 16, false>(T, tid); __syncthreads();
    dwt_pass<16, SH, SD, 1,  16, 16, false>(T, tid); __syncthreads();
    dwt_pass<16, SD, SH, 1,  16, 16, false>(T, tid); __syncthreads();

    // inverse level-1 reordered d, h, then w fused with the store (axis transforms commute)
    dwt_pass<32, SD, SH, 1, 32, 32, false>(T, tid); __syncthreads();
    dwt_pass<32, SH, SD, 1, 32, 32, false>(T, tid); __syncthreads();

    // ---- fused: inverse level-1 w-transform + global store (float4) ----
#pragma unroll
    for (int l = tid; l < 1024; l += NTHREADS) {
        int h = l & 31, d = l >> 5;
        const float* p = T + d*SD + h*SH;
        float4* g = reinterpret_cast<float4*>(y + gbase + d*25600 + h*160);
#pragma unroll
        for (int k = 0; k < 8; k++) {
            float lo0 = p[2*k],     hi0 = p[2*k + 16];
            float lo1 = p[2*k + 1], hi1 = p[2*k + 17];
            float4 q;
            q.x = (lo0 + hi0) * RS2; q.y = (lo0 - hi0) * RS2;
            q.z = (lo1 + hi1) * RS2; q.w = (lo1 - hi1) * RS2;
            g[k] = q;
        }
    }
}

extern "C" void kernel_launch(void* const* d_in, const int* in_sizes, int n_in,
                              void* d_out, int out_size) {
    const float* x = (const float*)d_in[0];
    float* y = (float*)d_out;
    (void)in_sizes; (void)n_in; (void)out_size;

    const size_t smem_bytes = (size_t)TILE_F * sizeof(float); // 139392 B
    cudaFuncSetAttribute(bandlet3d_kernel,
                         cudaFuncAttributeMaxDynamicSharedMemorySize, (int)smem_bytes);
    bandlet3d_kernel<<<250, NTHREADS, smem_bytes>>>(x, y);
}

// round 6
// speedup vs baseline: 1.1417x; 1.1417x over previous
#include <cuda_runtime.h>

#define RS2 0.7071067811865476f
#define TAU_V 0.05f

constexpr int SH = 33;
constexpr int SD = 1089;             // 33*33 ; both ≡1 mod 32 → conflict-free strided access
constexpr int TILE_F = 32 * SD;      // 34848 floats
constexpr int SBLK = 584;            // scratch block stride (≡8 mod 32; 73a+9b+c layout)
constexpr int SCR_F = 21 * SBLK;     // 12264 floats
constexpr int NTHREADS = 512;

// valid level-1 band-block slots (slot = d3*16 + h3*4 + w3, excluding lll octant)
__device__ __constant__ unsigned char VSLOT[56] = {
    2,3,6,7,8,9,10,11,12,13,14,15,18,19,22,23,
    24,25,26,27,28,29,30,31,32,33,34,35,36,37,38,39,
    40,41,42,43,44,45,46,47,48,49,50,51,52,53,54,55,
    56,57,58,59,60,61,62,63
};

extern __shared__ float smem[];

template<int N, int SLINE>
__device__ __forceinline__ void line_fwd(float* p) {
    float v[N];
#pragma unroll
    for (int k = 0; k < N; k++) v[k] = p[k * SLINE];
#pragma unroll
    for (int i = 0; i < N / 2; i++) {
        p[i * SLINE]         = (v[2*i] + v[2*i+1]) * RS2;
        p[(i + N/2) * SLINE] = (v[2*i] - v[2*i+1]) * RS2;
    }
}
template<int N, int SLINE>
__device__ __forceinline__ void line_inv(float* p) {
    float v[N];
#pragma unroll
    for (int k = 0; k < N; k++) v[k] = p[k * SLINE];
#pragma unroll
    for (int i = 0; i < N / 2; i++) {
        p[(2*i)   * SLINE] = (v[i] + v[i + N/2]) * RS2;
        p[(2*i+1) * SLINE] = (v[i] - v[i + N/2]) * RS2;
    }
}

template<int N, int SLINE, int SA, int SB, int NA, int NB, bool FWD>
__device__ __forceinline__ void dwt_pass(float* T, int tid) {
    for (int li = tid; li < NA * NB; li += NTHREADS) {
        int a = li / NB, b = li % NB;          // NB power of two → shifts
        float* p = T + a * SA + b * SB;
        if (FWD) line_fwd<N, SLINE>(p); else line_inv<N, SLINE>(p);
    }
}

// ---- 2D Haar pyramid fwd + soft-threshold + inv on v[64] in registers ----
__device__ __forceinline__ void pyramid(float* v) {
#pragma unroll
    for (int lev = 0; lev < 3; lev++) {
        const int S = 8 >> lev, H = S >> 1;
#pragma unroll
        for (int j = 0; j < S; j++) {
            float t[4], u[4];
#pragma unroll
            for (int i = 0; i < H; i++) {
                float a = v[(2*i)*8+j], b = v[(2*i+1)*8+j];
                t[i] = (a + b) * RS2; u[i] = (a - b) * RS2;
            }
#pragma unroll
            for (int i = 0; i < H; i++) { v[i*8+j] = t[i]; v[(i+H)*8+j] = u[i]; }
        }
#pragma unroll
        for (int i = 0; i < S; i++) {
            float t[4], u[4];
#pragma unroll
            for (int j = 0; j < H; j++) {
                float a = v[i*8+2*j], b = v[i*8+2*j+1];
                t[j] = (a + b) * RS2; u[j] = (a - b) * RS2;
            }
#pragma unroll
            for (int j = 0; j < H; j++) { v[i*8+j] = t[j]; v[i*8+j+H] = u[j]; }
        }
    }
#pragma unroll
    for (int e = 1; e < 64; e++)
        v[e] = copysignf(fmaxf(fabsf(v[e]) - TAU_V, 0.0f), v[e]);
#pragma unroll
    for (int lev = 2; lev >= 0; lev--) {
        const int S = 8 >> lev, H = S >> 1;
#pragma unroll
        for (int i = 0; i < S; i++) {
            float t[4], u[4];
#pragma unroll
            for (int j = 0; j < H; j++) {
                float lo = v[i*8+j], hi = v[i*8+j+H];
                t[j] = (lo + hi) * RS2; u[j] = (lo - hi) * RS2;
            }
#pragma unroll
            for (int j = 0; j < H; j++) { v[i*8+2*j] = t[j]; v[i*8+2*j+1] = u[j]; }
        }
#pragma unroll
        for (int j = 0; j < S; j++) {
            float t[4], u[4];
#pragma unroll
            for (int i = 0; i < H; i++) {
                float lo = v[i*8+j], hi = v[(i+H)*8+j];
                t[i] = (lo + hi) * RS2; u[i] = (lo - hi) * RS2;
            }
#pragma unroll
            for (int i = 0; i < H; i++) { v[(2*i)*8+j] = t[i]; v[(2*i+1)*8+j] = u[i]; }
        }
    }
}

// one bandlet group, 2 barriers: n0->T, n1->scratch (parallel, disjoint); then n2 merges.
// No trailing barrier — successive groups touch disjoint block regions.
__device__ __forceinline__ void bandlet_group(float* T, float* S, int nrm, bool active,
                                              int bd, int bh, int bw, int s, int sbase) {
    float v[64];
    if (active) {
        if (nrm == 0) {
            const float* p = T + (bd+s)*SD + bh*SH + bw;
#pragma unroll
            for (int i = 0; i < 8; i++)
#pragma unroll
                for (int j = 0; j < 8; j++) v[i*8+j] = p[i*SH + j];
        } else if (nrm == 1) {
            const float* p = T + bd*SD + (bh+s)*SH + bw;
#pragma unroll
            for (int i = 0; i < 8; i++)
#pragma unroll
                for (int j = 0; j < 8; j++) v[i*8+j] = p[i*SD + j];
        } else {
            const float* p = T + bd*SD + bh*SH + bw + s;
#pragma unroll
            for (int i = 0; i < 8; i++)
#pragma unroll
                for (int j = 0; j < 8; j++) v[i*8+j] = p[i*SD + j*SH];
        }
        pyramid(v);
    }
    __syncthreads();   // all reads of original band data complete
    if (active) {
        if (nrm == 0) {
            float* p = T + (bd+s)*SD + bh*SH + bw;
#pragma unroll
            for (int i = 0; i < 8; i++)
#pragma unroll
                for (int j = 0; j < 8; j++) p[i*SH + j] = v[i*8+j];
        } else if (nrm == 1) {
            float* q = S + sbase;                       // (a,b,c)=(i,s,j) -> 73i+9s+j
#pragma unroll
            for (int i = 0; i < 8; i++)
#pragma unroll
                for (int j = 0; j < 8; j++) q[73*i + 9*s + j] = v[i*8+j];
        }
    }
    __syncthreads();   // n0 (T) and n1 (S) visible
    if (active && nrm == 2) {
        float* p = T + bd*SD + bh*SH + bw + s;
        const float* q = S + sbase;                     // read (i,j,s) -> 73i+9j+s
#pragma unroll
        for (int i = 0; i < 8; i++)
#pragma unroll
            for (int j = 0; j < 8; j++)
                p[i*SD + j*SH] = (p[i*SD + j*SH] + q[73*i + 9*j + s] + v[i*8+j]) * (1.0f / 3.0f);
    }
}

__global__ __launch_bounds__(NTHREADS, 1)
void bandlet3d_kernel(const float* __restrict__ x, float* __restrict__ y) {
    float* T = smem;
    float* S = smem + TILE_F;
    const int tid = threadIdx.x;

    const int bc = blockIdx.x;
    const int batch = bc / 125;
    const int rem = bc - batch * 125;
    const int td = rem / 25;
    const int th = (rem / 5) % 5;
    const int tw = rem % 5;
    const long long gbase = (long long)batch * 4096000LL
                          + (long long)td * 32 * 25600 + th * 32 * 160 + tw * 32;

    // ---- fused coalesced load + level-1 w-transform (2 butterflies per float4) ----
    for (int l = tid; l < 8192; l += NTHREADS) {
        int w4 = l & 7, h = (l >> 3) & 31, d = l >> 8;     // w4 fastest → coalesced LDG.128
        float4 q = *reinterpret_cast<const float4*>(x + gbase + d*25600 + h*160 + w4*4);
        float* p = T + d*SD + h*SH;
        int i0 = 2 * w4;
        p[i0]          = (q.x + q.y) * RS2;
        p[i0 + 1]      = (q.z + q.w) * RS2;
        p[i0 + 16]     = (q.x - q.y) * RS2;
        p[i0 + 17]     = (q.z - q.w) * RS2;
    }
    __syncthreads();

    // forward level-1 h and d
    dwt_pass<32, SH, SD, 1, 32, 32, true>(T, tid); __syncthreads();
    dwt_pass<32, SD, SH, 1, 32, 32, true>(T, tid); __syncthreads();

    // ---- level-1 bandlet: 56 blocks in groups of 21/21/14 ----
#pragma unroll 1
    for (int g = 0; g < 3; g++) {
        const int base = g * 21;
        const int nblk = (g == 2) ? 14 : 21;
        const int ntask = nblk * 8;
        int nrm = 0, s = 0, bd = 0, bh = 0, bw = 0, sbase = 0;
        bool active = (tid < 3 * ntask);
        if (active) {
            nrm = tid / ntask;
            int r = tid - nrm * ntask;
            int bg = r >> 3; s = r & 7;
            sbase = bg * SBLK;
            int slot = VSLOT[base + bg];
            bd = ((slot >> 4) & 3) * 8;
            bh = ((slot >> 2) & 3) * 8;
            bw = (slot & 3) * 8;
        }
        bandlet_group(T, S, nrm, active, bd, bh, bw, s, sbase);
    }
    // no barrier: fwd level-2 touches only the lll region (disjoint from band blocks)

    // forward level-2 (w,h,d on [0:16)^3)
    dwt_pass<16, 1,  SD, SH, 16, 16, true>(T, tid); __syncthreads();
    dwt_pass<16, SH, SD, 1,  16, 16, true>(T, tid); __syncthreads();
    dwt_pass<16, SD, SH, 1,  16, 16, true>(T, tid); __syncthreads();

    // ---- level-2 bandlet: 7 blocks, 168 tasks ----
    {
        int nrm = 0, s = 0, bd = 0, bh = 0, bw = 0, sbase = 0;
        bool active = (tid < 168);
        if (active) {
            nrm = tid / 56;
            int r = tid - nrm * 56;
            int bg = r >> 3; s = r & 7;
            sbase = bg * SBLK;
            int slot = bg + 1;
            bd = ((slot >> 2) & 1) * 8;
            bh = ((slot >> 1) & 1) * 8;
            bw = (slot & 1) * 8;
        }
        bandlet_group(T, S, nrm, active, bd, bh, bw, s, sbase);
    }
    __syncthreads();   // idwt level-2 reads the band blocks just written

    // inverse level-2 (w,h,d)
    dwt_pass<16, 1,  SD, SH, 16, 16, false>(T, tid); __syncthreads();
    dwt_pass<16, SH, SD, 1,  16, 16, false>(T, tid); __syncthreads();
    dwt_pass<16, SD, SH, 1,  16, 16, false>(T, tid); __syncthreads();

    // inverse level-1: d, h, then w fused with the store (axis transforms commute)
    dwt_pass<32, SD, SH, 1, 32, 32, false>(T, tid); __syncthreads();
    dwt_pass<32, SH, SD, 1, 32, 32, false>(T, tid); __syncthreads();

    // ---- fused inverse level-1 w-transform + coalesced store ----
    for (int l = tid; l < 8192; l += NTHREADS) {
        int w4 = l & 7, h = (l >> 3) & 31, d = l >> 8;
        const float* p = T + d*SD + h*SH;
        int i0 = 2 * w4;
        float lo0 = p[i0],     hi0 = p[i0 + 16];
        float lo1 = p[i0 + 1], hi1 = p[i0 + 17];
        float4 q;
        q.x = (lo0 + hi0) * RS2; q.y = (lo0 - hi0) * RS2;
        q.z = (lo1 + hi1) * RS2; q.w = (lo1 - hi1) * RS2;
        *reinterpret_cast<float4*>(y + gbase + d*25600 + h*160 + w4*4) = q;
    }
}

extern "C" void kernel_launch(void* const* d_in, const int* in_sizes, int n_in,
                              void* d_out, int out_size) {
    const float* x = (const float*)d_in[0];
    float* y = (float*)d_out;
    (void)in_sizes; (void)n_in; (void)out_size;

    const size_t smem_bytes = (size_t)(TILE_F + SCR_F) * sizeof(float); // 188448 B
    cudaFuncSetAttribute(bandlet3d_kernel,
                         cudaFuncAttributeMaxDynamicSharedMemorySize, (int)smem_bytes);
    bandlet3d_kernel<<<250, NTHREADS, smem_bytes>>>(x, y);
}

// round 7
// speedup vs baseline: 1.2287x; 1.0762x over previous
#include <cuda_runtime.h>

#define RS2 0.7071067811865476f
#define TAU_V 0.05f

constexpr int SH = 33;
constexpr int SD = 1089;             // 33*33 ; both ≡1 mod 32 → conflict-free strided access
constexpr int TILE_F = 32 * SD;      // 34848 floats = 139392 B
constexpr int NTHREADS = 512;

// valid level-1 band-block slots (slot = d3*16 + h3*4 + w3, excluding lll octant)
__device__ __constant__ unsigned char VSLOT[56] = {
    2,3,6,7,8,9,10,11,12,13,14,15,18,19,22,23,
    24,25,26,27,28,29,30,31,32,33,34,35,36,37,38,39,
    40,41,42,43,44,45,46,47,48,49,50,51,52,53,54,55,
    56,57,58,59,60,61,62,63
};

extern __shared__ float smem[];

template<int N, int SLINE>
__device__ __forceinline__ void line_fwd(float* p) {
    float v[N];
#pragma unroll
    for (int k = 0; k < N; k++) v[k] = p[k * SLINE];
#pragma unroll
    for (int i = 0; i < N / 2; i++) {
        p[i * SLINE]         = (v[2*i] + v[2*i+1]) * RS2;
        p[(i + N/2) * SLINE] = (v[2*i] - v[2*i+1]) * RS2;
    }
}
template<int N, int SLINE>
__device__ __forceinline__ void line_inv(float* p) {
    float v[N];
#pragma unroll
    for (int k = 0; k < N; k++) v[k] = p[k * SLINE];
#pragma unroll
    for (int i = 0; i < N / 2; i++) {
        p[(2*i)   * SLINE] = (v[i] + v[i + N/2]) * RS2;
        p[(2*i+1) * SLINE] = (v[i] - v[i + N/2]) * RS2;
    }
}

template<int N, int SLINE, int SA, int SB, int NA, int NB, bool FWD>
__device__ __forceinline__ void dwt_pass(float* T, int tid) {
    for (int li = tid; li < NA * NB; li += NTHREADS) {
        int a = li / NB, b = li % NB;          // NB power of two → shifts
        float* p = T + a * SA + b * SB;
        if (FWD) line_fwd<N, SLINE>(p); else line_inv<N, SLINE>(p);
    }
}

// ---- 2D Haar pyramid fwd + soft-threshold + inv on v[64] in registers ----
__device__ __forceinline__ void pyramid(float* v) {
#pragma unroll
    for (int lev = 0; lev < 3; lev++) {
        const int S = 8 >> lev, H = S >> 1;
#pragma unroll
        for (int j = 0; j < S; j++) {
            float t[4], u[4];
#pragma unroll
            for (int i = 0; i < H; i++) {
                float a = v[(2*i)*8+j], b = v[(2*i+1)*8+j];
                t[i] = (a + b) * RS2; u[i] = (a - b) * RS2;
            }
#pragma unroll
            for (int i = 0; i < H; i++) { v[i*8+j] = t[i]; v[(i+H)*8+j] = u[i]; }
        }
#pragma unroll
        for (int i = 0; i < S; i++) {
            float t[4], u[4];
#pragma unroll
            for (int j = 0; j < H; j++) {
                float a = v[i*8+2*j], b = v[i*8+2*j+1];
                t[j] = (a + b) * RS2; u[j] = (a - b) * RS2;
            }
#pragma unroll
            for (int j = 0; j < H; j++) { v[i*8+j] = t[j]; v[i*8+j+H] = u[j]; }
        }
    }
#pragma unroll
    for (int e = 1; e < 64; e++)
        v[e] = copysignf(fmaxf(fabsf(v[e]) - TAU_V, 0.0f), v[e]);
#pragma unroll
    for (int lev = 2; lev >= 0; lev--) {
        const int S = 8 >> lev, H = S >> 1;
#pragma unroll
        for (int i = 0; i < S; i++) {
            float t[4], u[4];
#pragma unroll
            for (int j = 0; j < H; j++) {
                float lo = v[i*8+j], hi = v[i*8+j+H];
                t[j] = (lo + hi) * RS2; u[j] = (lo - hi) * RS2;
            }
#pragma unroll
            for (int j = 0; j < H; j++) { v[i*8+2*j] = t[j]; v[i*8+2*j+1] = u[j]; }
        }
#pragma unroll
        for (int j = 0; j < S; j++) {
            float t[4], u[4];
#pragma unroll
            for (int i = 0; i < H; i++) {
                float lo = v[i*8+j], hi = v[(i+H)*8+j];
                t[i] = (lo + hi) * RS2; u[i] = (lo - hi) * RS2;
            }
#pragma unroll
            for (int i = 0; i < H; i++) { v[(2*i)*8+j] = t[i]; v[(2*i+1)*8+j] = u[i]; }
        }
    }
}

// R4-style group: compute, then 3 ordered in-T writeback phases (n0 store, n1 +=, n2 merge/3).
// No trailing barrier — successive groups touch disjoint block regions.
__device__ __forceinline__ void bandlet_group(float* T, int nrm, bool active,
                                              int bd, int bh, int bw, int s) {
    float v[64];
    if (active) {
        if (nrm == 0) {
            const float* p = T + (bd+s)*SD + bh*SH + bw;
#pragma unroll
            for (int i = 0; i < 8; i++)
#pragma unroll
                for (int j = 0; j < 8; j++) v[i*8+j] = p[i*SH + j];
        } else if (nrm == 1) {
            const float* p = T + bd*SD + (bh+s)*SH + bw;
#pragma unroll
            for (int i = 0; i < 8; i++)
#pragma unroll
                for (int j = 0; j < 8; j++) v[i*8+j] = p[i*SD + j];
        } else {
            const float* p = T + bd*SD + bh*SH + bw + s;
#pragma unroll
            for (int i = 0; i < 8; i++)
#pragma unroll
                for (int j = 0; j < 8; j++) v[i*8+j] = p[i*SD + j*SH];
        }
        pyramid(v);
    }
    __syncthreads();
    if (active && nrm == 0) {
        float* p = T + (bd+s)*SD + bh*SH + bw;
#pragma unroll
        for (int i = 0; i < 8; i++)
#pragma unroll
            for (int j = 0; j < 8; j++) p[i*SH + j] = v[i*8+j];
    }
    __syncthreads();
    if (active && nrm == 1) {
        float* p = T + bd*SD + (bh+s)*SH + bw;
#pragma unroll
        for (int i = 0; i < 8; i++)
#pragma unroll
            for (int j = 0; j < 8; j++) p[i*SD + j] += v[i*8+j];
    }
    __syncthreads();
    if (active && nrm == 2) {
        float* p = T + bd*SD + bh*SH + bw + s;
#pragma unroll
        for (int i = 0; i < 8; i++)
#pragma unroll
            for (int j = 0; j < 8; j++)
                p[i*SD + j*SH] = (p[i*SD + j*SH] + v[i*8+j]) * (1.0f / 3.0f);
    }
}

__global__ __launch_bounds__(NTHREADS, 1)
void bandlet3d_kernel(const float* __restrict__ x, float* __restrict__ y) {
    float* T = smem;
    const int tid = threadIdx.x;

    const int bc = blockIdx.x;
    const int batch = bc / 125;
    const int rem = bc - batch * 125;
    const int td = rem / 25;
    const int th = (rem / 5) % 5;
    const int tw = rem % 5;
    const long long gbase = (long long)batch * 4096000LL
                          + (long long)td * 32 * 25600 + th * 32 * 160 + tw * 32;

    // ---- fused coalesced load + level-1 w-transform (2 butterflies per float4) ----
    for (int l = tid; l < 8192; l += NTHREADS) {
        int w4 = l & 7, h = (l >> 3) & 31, d = l >> 8;     // w4 fastest → coalesced LDG.128
        float4 q = *reinterpret_cast<const float4*>(x + gbase + d*25600 + h*160 + w4*4);
        float* p = T + d*SD + h*SH;
        int i0 = 2 * w4;
        p[i0]      = (q.x + q.y) * RS2;
        p[i0 + 1]  = (q.z + q.w) * RS2;
        p[i0 + 16] = (q.x - q.y) * RS2;
        p[i0 + 17] = (q.z - q.w) * RS2;
    }
    __syncthreads();

    // forward level-1 h and d
    dwt_pass<32, SH, SD, 1, 32, 32, true>(T, tid); __syncthreads();
    dwt_pass<32, SD, SH, 1, 32, 32, true>(T, tid); __syncthreads();

    // ---- level-1 bandlet: 56 blocks in groups of 21/21/14 (compiler may unroll) ----
    for (int g = 0; g < 3; g++) {
        const int base = g * 21;
        const int nblk = (g == 2) ? 14 : 21;
        const int ntask = nblk * 8;
        int nrm = 3, s = 0, bd = 0, bh = 0, bw = 0;
        bool active = (tid < 3 * ntask);
        if (active) {
            nrm = tid / ntask;
            int r = tid - nrm * ntask;
            int bg = r >> 3; s = r & 7;
            int slot = VSLOT[base + bg];
            bd = ((slot >> 4) & 3) * 8;
            bh = ((slot >> 2) & 3) * 8;
            bw = (slot & 3) * 8;
        }
        bandlet_group(T, nrm, active, bd, bh, bw, s);
    }
    // no barrier: fwd level-2 touches only the lll region (disjoint from band blocks)

    // forward level-2 (w,h,d on [0:16)^3)
    dwt_pass<16, 1,  SD, SH, 16, 16, true>(T, tid); __syncthreads();
    dwt_pass<16, SH, SD, 1,  16, 16, true>(T, tid); __syncthreads();
    dwt_pass<16, SD, SH, 1,  16, 16, true>(T, tid); __syncthreads();

    // ---- level-2 bandlet: 7 blocks, 168 tasks ----
    {
        int nrm = 3, s = 0, bd = 0, bh = 0, bw = 0;
        bool active = (tid < 168);
        if (active) {
            nrm = tid / 56;
            int r = tid - nrm * 56;
            int bg = r >> 3; s = r & 7;
            int slot = bg + 1;
            bd = ((slot >> 2) & 1) * 8;
            bh = ((slot >> 1) & 1) * 8;
            bw = (slot & 1) * 8;
        }
        bandlet_group(T, nrm, active, bd, bh, bw, s);
    }
    __syncthreads();   // idwt level-2 reads the band blocks just written

    // inverse level-2 (w,h,d)
    dwt_pass<16, 1,  SD, SH, 16, 16, false>(T, tid); __syncthreads();
    dwt_pass<16, SH, SD, 1,  16, 16, false>(T, tid); __syncthreads();
    dwt_pass<16, SD, SH, 1,  16, 16, false>(T, tid); __syncthreads();

    // inverse level-1: d, h, then w fused with the store (axis transforms commute)
    dwt_pass<32, SD, SH, 1, 32, 32, false>(T, tid); __syncthreads();
    dwt_pass<32, SH, SD, 1, 32, 32, false>(T, tid); __syncthreads();

    // ---- fused inverse level-1 w-transform + coalesced store ----
    for (int l = tid; l < 8192; l += NTHREADS) {
        int w4 = l & 7, h = (l >> 3) & 31, d = l >> 8;
        const float* p = T + d*SD + h*SH;
        int i0 = 2 * w4;
        float lo0 = p[i0],     hi0 = p[i0 + 16];
        float lo1 = p[i0 + 1], hi1 = p[i0 + 17];
        float4 q;
        q.x = (lo0 + hi0) * RS2; q.y = (lo0 - hi0) * RS2;
        q.z = (lo1 + hi1) * RS2; q.w = (lo1 - hi1) * RS2;
        *reinterpret_cast<float4*>(y + gbase + d*25600 + h*160 + w4*4) = q;
    }
}

extern "C" void kernel_launch(void* const* d_in, const int* in_sizes, int n_in,
                              void* d_out, int out_size) {
    const float* x = (const float*)d_in[0];
    float* y = (float*)d_out;
    (void)in_sizes; (void)n_in; (void)out_size;

    const size_t smem_bytes = (size_t)TILE_F * sizeof(float); // 139392 B
    cudaFuncSetAttribute(bandlet3d_kernel,
                         cudaFuncAttributeMaxDynamicSharedMemorySize, (int)smem_bytes);
    bandlet3d_kernel<<<250, NTHREADS, smem_bytes>>>(x, y);
}